// round 7
// baseline (speedup 1.0000x reference)
#include <cuda_runtime.h>
#include <math.h>

#define DD 128
#define NMAX 100000
#define EMAX 1600000
#define LUTN 2048
#define NNL 8192       // nearest-neighbor sigmoid table (gate kernel)
#define LNEPS 1e-5f
#define AS_STRIDE 132  // 128-row A tile, padded stride

typedef unsigned long long ull;

// ---------------- scratch (static device globals) ---------------------------
__device__ float  g_ax[NMAX * DD];     // silu(x @ agg_W + b)
__device__ float  g_agg[NMAX * DD];    // mean-aggregated messages
__device__ int    g_cnti[NMAX];        // in-degree
__device__ int    g_rows[NMAX + 1];    // CSR row offsets
__device__ int    g_cur[NMAX];         // scatter cursors
__device__ int    g_csr_src[EMAX];     // CSR: source node per slot
__device__ float  g_csr_w[EMAX];       // CSR: edge gate per slot
__device__ float2 g_lut[LUTN + 1];     // interp sigmoid {s_i - i*d_i, d_i}
__device__ float  g_nn[NNL];           // nearest-neighbor sigmoid table

// ---------------- packed f32x2 helpers ---------------------------------------
__device__ __forceinline__ ull pack_dup(float a) {
    unsigned int au = __float_as_uint(a);
    ull r;
    asm("mov.b64 %0, {%1, %1};" : "=l"(r) : "r"(au));
    return r;
}
__device__ __forceinline__ ull pack2(float lo, float hi) {
    ull r;
    asm("mov.b64 %0, {%1, %2};" : "=l"(r) : "r"(__float_as_uint(lo)), "r"(__float_as_uint(hi)));
    return r;
}
__device__ __forceinline__ void fma2(ull& d, ull a, ull b) {
    asm("fma.rn.f32x2 %0, %1, %2, %0;" : "+l"(d) : "l"(a), "l"(b));
}
__device__ __forceinline__ ull mul2(ull a, ull b) {
    ull r;
    asm("mul.rn.f32x2 %0, %1, %2;" : "=l"(r) : "l"(a), "l"(b));
    return r;
}
__device__ __forceinline__ void unpack2(ull v, float& lo, float& hi) {
    unsigned int l, h;
    asm("mov.b64 {%0, %1}, %2;" : "=r"(l), "=r"(h) : "l"(v));
    lo = __uint_as_float(l); hi = __uint_as_float(h);
}

// ---------------- LUT build + count zero (fused) ------------------------------
__global__ void k_lut_zcnt(int n) {
    int stride = blockDim.x * gridDim.x;
    for (int i = threadIdx.x + blockIdx.x * blockDim.x; i <= LUTN; i += stride) {
        float z0 = -8.f + (float)i * (16.f / LUTN);
        float z1 = z0 + (16.f / LUTN);
        float s0 = 1.f / (1.f + expf(-z0));
        float s1 = 1.f / (1.f + expf(-z1));
        float d  = s1 - s0;
        g_lut[i] = make_float2(s0 - (float)i * d, d);
    }
    for (int i = threadIdx.x + blockIdx.x * blockDim.x; i < NNL; i += stride) {
        float z = -8.f + ((float)i + 0.5f) * (16.f / NNL);
        g_nn[i] = 1.f / (1.f + expf(-z));
    }
    for (int i = threadIdx.x + blockIdx.x * blockDim.x; i < n; i += stride)
        g_cnti[i] = 0;
}

__device__ __forceinline__ float lut_sigma_g(float z) {
    float t = fminf(fmaxf(fmaf(z, 128.f, 1024.f), 0.f), 2047.99f);
    float2 e = __ldg(&g_lut[(int)t]);
    return fmaf(e.y, t, e.x);
}
__device__ __forceinline__ float nn_sigma(const float* tab, float z) {
    float t = fminf(fmaxf(fmaf(z, 512.f, 4096.f), 0.f), 8191.f);
    return tab[(int)t];
}

// ---------------- CSR build ----------------------------------------------------
__global__ void k_count(const int* __restrict__ ei, int E) {
    int stride = blockDim.x * gridDim.x;
    for (int i = threadIdx.x + blockIdx.x * blockDim.x; i < E; i += stride)
        atomicAdd(&g_cnti[__ldg(&ei[E + i])], 1);
}

__global__ void __launch_bounds__(1024)
k_scan_fused(int n, int E) {
    __shared__ int sh[1024];
    int t = threadIdx.x;
    int len = (n + 1023) / 1024;
    int s = t * len;
    int e = min(s + len, n);
    int sum = 0;
    for (int i = s; i < e; i++) sum += g_cnti[i];
    sh[t] = sum;
    __syncthreads();
    for (int o = 1; o < 1024; o <<= 1) {
        int u = (t >= o) ? sh[t - o] : 0;
        __syncthreads();
        sh[t] += u;
        __syncthreads();
    }
    int excl = sh[t] - sum;
    for (int i = s; i < e; i++) {
        int c = g_cnti[i];
        g_rows[i] = excl;
        g_cur[i]  = excl;
        excl += c;
    }
    if (t == 0) g_rows[n] = E;
}

// ---------------- edge gate + CSR permute (THREAD per edge, NN sigma) ----------
__global__ void __launch_bounds__(256)
k_gate(const int* __restrict__ ei, const float* __restrict__ ea,
       const float* __restrict__ W1, const float* __restrict__ b1,
       const float* __restrict__ W2, const float* __restrict__ b2p, int E) {
    __shared__ float nn[NNL];          // 32 KB
    __shared__ ull w1s[4][64];
    __shared__ ull b1s[64];
    __shared__ ull w2s[64];

    for (int i = threadIdx.x; i < NNL; i += blockDim.x) nn[i] = g_nn[i];
    if (threadIdx.x < 64) {
        int c2 = threadIdx.x;
#pragma unroll
        for (int k = 0; k < 4; k++)
            w1s[k][c2] = __ldg((const ull*)(W1 + k * DD) + c2);
        b1s[c2] = __ldg((const ull*)b1 + c2);
        w2s[c2] = __ldg((const ull*)W2 + c2);
    }
    __syncthreads();

    float b2v = __ldg(b2p);
    int stride = blockDim.x * gridDim.x;

    for (int e = threadIdx.x + blockIdx.x * blockDim.x; e < E; e += stride) {
        int src = __ldg(&ei[e]);
        int dst = __ldg(&ei[E + e]);
        float4 a = __ldg((const float4*)(ea + 4 * e));
        ull ax = pack_dup(a.x), ay = pack_dup(a.y);
        ull az = pack_dup(a.z), aw = pack_dup(a.w);

        ull dot2 = 0ull;
#pragma unroll 16
        for (int c2 = 0; c2 < 64; c2++) {
            ull zz = b1s[c2];
            fma2(zz, ax, w1s[0][c2]);
            fma2(zz, ay, w1s[1][c2]);
            fma2(zz, az, w1s[2][c2]);
            fma2(zz, aw, w1s[3][c2]);
            float z0, z1;
            unpack2(zz, z0, z1);
            float s0 = nn_sigma(nn, z0);
            float s1 = nn_sigma(nn, z1);
            ull zs = mul2(zz, pack2(s0, s1));   // silu = z * sigma(z)
            fma2(dot2, zs, w2s[c2]);
        }
        float d0, d1;
        unpack2(dot2, d0, d1);
        float ew = nn_sigma(nn, d0 + d1 + b2v);

        int pos = atomicAdd(&g_cur[dst], 1);
        g_csr_src[pos] = src;
        g_csr_w[pos]   = ew;
    }
}

// ---------------- gather: mean-aggregate gated messages (warp per node) --------
__global__ void __launch_bounds__(256)
k_gather(int n) {
    int lane  = threadIdx.x & 31;
    int w     = (blockIdx.x * blockDim.x + threadIdx.x) >> 5;
    int nwarp = (gridDim.x * blockDim.x) >> 5;

    for (int i = w; i < n; i += nwarp) {
        int s = g_rows[i], e = g_rows[i + 1];
        float4 a0 = make_float4(0.f, 0.f, 0.f, 0.f);
        float4 a1 = make_float4(0.f, 0.f, 0.f, 0.f);
        float4 a2 = make_float4(0.f, 0.f, 0.f, 0.f);
        float4 a3 = make_float4(0.f, 0.f, 0.f, 0.f);
        int j = s;
        for (; j + 3 < e; j += 4) {
            int   s0 = __ldg(&g_csr_src[j]);
            int   s1 = __ldg(&g_csr_src[j + 1]);
            int   s2 = __ldg(&g_csr_src[j + 2]);
            int   s3 = __ldg(&g_csr_src[j + 3]);
            float w0 = __ldg(&g_csr_w[j]);
            float w1 = __ldg(&g_csr_w[j + 1]);
            float w2 = __ldg(&g_csr_w[j + 2]);
            float w3 = __ldg(&g_csr_w[j + 3]);
            float4 v0 = __ldg((const float4*)(g_ax + s0 * DD + lane * 4));
            float4 v1 = __ldg((const float4*)(g_ax + s1 * DD + lane * 4));
            float4 v2 = __ldg((const float4*)(g_ax + s2 * DD + lane * 4));
            float4 v3 = __ldg((const float4*)(g_ax + s3 * DD + lane * 4));
            a0.x = fmaf(w0, v0.x, a0.x); a0.y = fmaf(w0, v0.y, a0.y);
            a0.z = fmaf(w0, v0.z, a0.z); a0.w = fmaf(w0, v0.w, a0.w);
            a1.x = fmaf(w1, v1.x, a1.x); a1.y = fmaf(w1, v1.y, a1.y);
            a1.z = fmaf(w1, v1.z, a1.z); a1.w = fmaf(w1, v1.w, a1.w);
            a2.x = fmaf(w2, v2.x, a2.x); a2.y = fmaf(w2, v2.y, a2.y);
            a2.z = fmaf(w2, v2.z, a2.z); a2.w = fmaf(w2, v2.w, a2.w);
            a3.x = fmaf(w3, v3.x, a3.x); a3.y = fmaf(w3, v3.y, a3.y);
            a3.z = fmaf(w3, v3.z, a3.z); a3.w = fmaf(w3, v3.w, a3.w);
        }
        for (; j < e; j++) {
            int   s0 = __ldg(&g_csr_src[j]);
            float w0 = __ldg(&g_csr_w[j]);
            float4 v0 = __ldg((const float4*)(g_ax + s0 * DD + lane * 4));
            a0.x = fmaf(w0, v0.x, a0.x); a0.y = fmaf(w0, v0.y, a0.y);
            a0.z = fmaf(w0, v0.z, a0.z); a0.w = fmaf(w0, v0.w, a0.w);
        }
        float rv = 1.f / fmaxf((float)(e - s), 1.f);
        float4 o;
        o.x = (a0.x + a1.x + a2.x + a3.x) * rv;
        o.y = (a0.y + a1.y + a2.y + a3.y) * rv;
        o.z = (a0.z + a1.z + a2.z + a3.z) * rv;
        o.w = (a0.w + a1.w + a2.w + a3.w) * rv;
        *(float4*)(g_agg + i * DD + lane * 4) = o;
    }
}

// ---------------- GEMM building blocks (split-k: Ws = 64x128 half) -------------
// smem: Ws[64][128] (32KB) + As[128][AS_STRIDE] (67.6KB) = 100KB -> 2 blocks/SM.
__device__ __forceinline__ void load_Wh(float* Ws, const float* __restrict__ W,
                                        int khalf, int tid) {
    const float4* s = (const float4*)(W + khalf * 64 * DD);
    float4* d = (float4*)Ws;
#pragma unroll
    for (int i = 0; i < 8; i++)        // 64*32 float4 / 256 threads
        d[tid + 256 * i] = s[tid + 256 * i];
}

__device__ __forceinline__ void load_A(float* As, const float* __restrict__ A,
                                       int row0, int n, int tid) {
#pragma unroll
    for (int it = 0; it < 16; it++) {
        int i = tid + 256 * it;
        int r = i >> 5, q = i & 31;
        int gr = row0 + r;
        float4 v = make_float4(0.f, 0.f, 0.f, 0.f);
        if (gr < n) v = ((const float4*)(A + gr * DD))[q];
        ((float4*)(As + r * AS_STRIDE))[q] = v;
    }
}

// 64-k half pass; A read at column offset kbase
__device__ __forceinline__ void mma8h(const float* Ws, const float* As,
                                      int tx, int ty, ull acc[8][4], int kbase) {
    const float* arow = As + ty * 8 * AS_STRIDE + kbase;
    const float* bcol = Ws + tx * 8;
#pragma unroll 4
    for (int k0 = 0; k0 < 64; k0 += 2) {
        float2 a[8];
#pragma unroll
        for (int r = 0; r < 8; r++)
            a[r] = *(const float2*)(arow + r * AS_STRIDE + k0);
        ulonglong2 p0 = *(const ulonglong2*)(bcol + k0 * DD);
        ulonglong2 p1 = *(const ulonglong2*)(bcol + k0 * DD + 4);
        ulonglong2 p2 = *(const ulonglong2*)(bcol + (k0 + 1) * DD);
        ulonglong2 p3 = *(const ulonglong2*)(bcol + (k0 + 1) * DD + 4);
        ull bb0[4] = {p0.x, p0.y, p1.x, p1.y};
        ull bb1[4] = {p2.x, p2.y, p3.x, p3.y};
#pragma unroll
        for (int r = 0; r < 8; r++) {
            ull aa0 = pack_dup(a[r].x);
#pragma unroll
            for (int c = 0; c < 4; c++) fma2(acc[r][c], aa0, bb0[c]);
            ull aa1 = pack_dup(a[r].y);
#pragma unroll
            for (int c = 0; c < 4; c++) fma2(acc[r][c], aa1, bb1[c]);
        }
    }
}

// full 128-k GEMM accumulate: A(As) @ W -> acc, W loaded in two halves
__device__ __forceinline__ void gemm128(float* Ws, const float* As,
                                        const float* __restrict__ W,
                                        int tx, int ty, int tid, ull acc[8][4]) {
    load_Wh(Ws, W, 0, tid);
    __syncthreads();
    mma8h(Ws, As, tx, ty, acc, 0);
    __syncthreads();
    load_Wh(Ws, W, 1, tid);
    __syncthreads();
    mma8h(Ws, As, tx, ty, acc, 64);
    __syncthreads();
}

// ---------------- K1: g_ax = silu(x @ agg_W + agg_b) ---------------------------
__global__ void __launch_bounds__(256, 2)
k_agg(const float* __restrict__ x, const float* __restrict__ W,
      const float* __restrict__ bias, int n) {
    extern __shared__ float smem[];
    float* Ws = smem;                 // 64*128
    float* As = smem + 64 * DD;       // 128*AS_STRIDE
    int tid = threadIdx.x;
    int row0 = blockIdx.x * 128;
    int tx = tid & 15, ty = tid >> 4;

    load_A(As, x, row0, n, tid);

    ull acc[8][4];
#pragma unroll
    for (int r = 0; r < 8; r++)
#pragma unroll
        for (int c = 0; c < 4; c++) acc[r][c] = 0ull;

    gemm128(Ws, As, W, tx, ty, tid, acc);

    float bv[8];
#pragma unroll
    for (int c = 0; c < 8; c++) bv[c] = bias[tx * 8 + c];
#pragma unroll
    for (int r = 0; r < 8; r++) {
        int gr = row0 + ty * 8 + r;
        if (gr < n) {
            float4 o0, o1;
            float* po0 = &o0.x;
            float* po1 = &o1.x;
#pragma unroll
            for (int c = 0; c < 4; c++) {
                float lo, hi;
                unpack2(acc[r][c], lo, hi);
                float z0 = lo + bv[2 * c], z1 = hi + bv[2 * c + 1];
                float v0 = z0 * lut_sigma_g(z0);
                float v1 = z1 * lut_sigma_g(z1);
                if (c < 2) { po0[2 * c] = v0; po0[2 * c + 1] = v1; }
                else       { po1[2 * (c - 2)] = v0; po1[2 * (c - 2) + 1] = v1; }
            }
            *(float4*)(g_ax + gr * DD + tx * 8)     = o0;
            *(float4*)(g_ax + gr * DD + tx * 8 + 4) = o1;
        }
    }
}

// ---------------- fused update: out = LN(silu([x|agg]@W1+b1)@W2 + b2 + x@resW) --
__global__ void __launch_bounds__(256, 2)
k_upd12(const float* __restrict__ x,
        const float* __restrict__ W1, const float* __restrict__ b1,
        const float* __restrict__ W2, const float* __restrict__ b2,
        const float* __restrict__ resW,
        const float* __restrict__ lng, const float* __restrict__ lnb,
        float* __restrict__ out, int n) {
    extern __shared__ float smem[];
    float* Ws = smem;
    float* As = smem + 64 * DD;
    int tid = threadIdx.x;
    int row0 = blockIdx.x * 128;
    int tx = tid & 15, ty = tid >> 4;

    ull acc[8][4];
#pragma unroll
    for (int r = 0; r < 8; r++)
#pragma unroll
        for (int c = 0; c < 4; c++) acc[r][c] = 0ull;

    // GEMM A: x @ W1[:128]
    load_A(As, x, row0, n, tid);
    gemm128(Ws, As, W1, tx, ty, tid, acc);

    // GEMM B: agg @ W1[128:]
    load_A(As, g_agg, row0, n, tid);
    gemm128(Ws, As, W1 + DD * DD, tx, ty, tid, acc);

    // stage h1 = silu(acc + b1) into As
    {
        float bv[8];
#pragma unroll
        for (int c = 0; c < 8; c++) bv[c] = b1[tx * 8 + c];
        __syncthreads();   // everyone done reading As from GEMM B
#pragma unroll
        for (int r = 0; r < 8; r++) {
            float* o = As + (ty * 8 + r) * AS_STRIDE + tx * 8;
            float4 o0, o1;
            float* po0 = &o0.x;
            float* po1 = &o1.x;
#pragma unroll
            for (int c = 0; c < 4; c++) {
                float lo, hi;
                unpack2(acc[r][c], lo, hi);
                float z0 = lo + bv[2 * c], z1 = hi + bv[2 * c + 1];
                float v0 = z0 * lut_sigma_g(z0);
                float v1 = z1 * lut_sigma_g(z1);
                if (c < 2) { po0[2 * c] = v0; po0[2 * c + 1] = v1; }
                else       { po1[2 * (c - 2)] = v0; po1[2 * (c - 2) + 1] = v1; }
            }
            *(float4*)(o)     = o0;
            *(float4*)(o + 4) = o1;
        }
    }
    __syncthreads();

    // GEMM C: h1 @ W2
#pragma unroll
    for (int r = 0; r < 8; r++)
#pragma unroll
        for (int c = 0; c < 4; c++) acc[r][c] = 0ull;
    gemm128(Ws, As, W2, tx, ty, tid, acc);

    // GEMM D: x @ resW
    load_A(As, x, row0, n, tid);
    gemm128(Ws, As, resW, tx, ty, tid, acc);

    // stage acc + b2 into As
    {
        float bv[8];
#pragma unroll
        for (int c = 0; c < 8; c++) bv[c] = b2[tx * 8 + c];
        __syncthreads();
#pragma unroll
        for (int r = 0; r < 8; r++) {
            float* o = As + (ty * 8 + r) * AS_STRIDE + tx * 8;
            float4 o0, o1;
            float* po0 = &o0.x;
            float* po1 = &o1.x;
#pragma unroll
            for (int c = 0; c < 4; c++) {
                float lo, hi;
                unpack2(acc[r][c], lo, hi);
                float v0 = lo + bv[2 * c];
                float v1 = hi + bv[2 * c + 1];
                if (c < 2) { po0[2 * c] = v0; po0[2 * c + 1] = v1; }
                else       { po1[2 * (c - 2)] = v0; po1[2 * (c - 2) + 1] = v1; }
            }
            *(float4*)(o)     = o0;
            *(float4*)(o + 4) = o1;
        }
    }
    __syncthreads();

    // LayerNorm epilogue
    int lane = tid & 31, w = tid >> 5;
    float4 gv = *(const float4*)(lng + lane * 4);
    float4 bb = *(const float4*)(lnb + lane * 4);
#pragma unroll
    for (int rr = 0; rr < 16; rr++) {
        int r = w * 16 + rr;
        int gr = row0 + r;
        float4 v = *(const float4*)(As + r * AS_STRIDE + lane * 4);
        float s = v.x + v.y + v.z + v.w;
        float q = v.x * v.x + v.y * v.y + v.z * v.z + v.w * v.w;
#pragma unroll
        for (int o = 16; o > 0; o >>= 1) {
            s += __shfl_xor_sync(0xffffffffu, s, o);
            q += __shfl_xor_sync(0xffffffffu, q, o);
        }
        float mu  = s * (1.f / 128.f);
        float var = q * (1.f / 128.f) - mu * mu;
        float rs  = rsqrtf(var + LNEPS);
        if (gr < n) {
            float4 ov;
            ov.x = (v.x - mu) * rs * gv.x + bb.x;
            ov.y = (v.y - mu) * rs * gv.y + bb.y;
            ov.z = (v.z - mu) * rs * gv.z + bb.z;
            ov.w = (v.w - mu) * rs * gv.w + bb.w;
            *(float4*)(out + gr * DD + lane * 4) = ov;
        }
    }
}

// ---------------- launch --------------------------------------------------------
extern "C" void kernel_launch(void* const* d_in, const int* in_sizes, int n_in,
                              void* d_out, int out_size) {
    const float* x    = (const float*)d_in[0];
    const int*   ei   = (const int*)  d_in[1];
    const float* ea   = (const float*)d_in[2];
    const float* aggW = (const float*)d_in[3];
    const float* aggb = (const float*)d_in[4];
    const float* eW1  = (const float*)d_in[5];
    const float* eb1  = (const float*)d_in[6];
    const float* eW2  = (const float*)d_in[7];
    const float* eb2  = (const float*)d_in[8];
    const float* uW1  = (const float*)d_in[9];
    const float* ub1  = (const float*)d_in[10];
    const float* uW2  = (const float*)d_in[11];
    const float* ub2  = (const float*)d_in[12];
    const float* lng  = (const float*)d_in[13];
    const float* lnb  = (const float*)d_in[14];
    const float* resW = (const float*)d_in[15];

    int n = in_sizes[0] / DD;
    int E = in_sizes[2] / 4;

    int dyn = (64 * DD + 128 * AS_STRIDE) * (int)sizeof(float);   // 100352 B
    cudaFuncSetAttribute(k_agg,   cudaFuncAttributeMaxDynamicSharedMemorySize, dyn);
    cudaFuncSetAttribute(k_upd12, cudaFuncAttributeMaxDynamicSharedMemorySize, dyn);

    int gblocks = (n + 127) / 128;

    // 4th launch is the profiled one -> k_gate (verify NN-table effect)
    k_lut_zcnt<<<512, 256>>>(n);                                   // 1
    k_count<<<1024, 256>>>(ei, E);                                 // 2
    k_scan_fused<<<1, 1024>>>(n, E);                               // 3
    k_gate<<<1480, 256>>>(ei, ea, eW1, eb1, eW2, eb2, E);          // 4  <- profiled
    k_agg<<<gblocks, 256, dyn>>>(x, aggW, aggb, n);                // 5
    k_gather<<<2048, 256>>>(n);                                    // 6
    k_upd12<<<gblocks, 256, dyn>>>(x, uW1, ub1, uW2, ub2, resW,
                                   lng, lnb, (float*)d_out, n);    // 7
}

// round 10
// speedup vs baseline: 1.3010x; 1.3010x over previous
#include <cuda_runtime.h>
#include <cuda_bf16.h>
#include <cstdint>
#include <math.h>

#define DD 128
#define NMAX 100000
#define EMAX 1600000
#define LUTN 2048
#define NNL 8192
#define LNEPS 1e-5f
#define TSTRIDE 136                    // bf16 elems per smem tile row (bank-safe)
#define TBYTES (128 * TSTRIDE * 2)     // 34816 bytes per 128x128 bf16 tile

typedef unsigned long long ull;

// ---------------- scratch (static device globals) ---------------------------
__device__ float  g_ax[NMAX * DD];
__device__ float  g_agg[NMAX * DD];
__device__ int    g_cnti[NMAX];
__device__ int    g_rows[NMAX + 1];
__device__ int    g_cur[NMAX];
__device__ int    g_csr_src[EMAX];
__device__ float  g_csr_w[EMAX];
__device__ float2 g_lut[LUTN + 1];     // interp sigmoid {s_i - i*d_i, d_i}
__device__ float  g_nn[NNL];           // NN sigmoid table (gate)
// pre-split transposed bf16 weights, [N rows][K cols] stride TSTRIDE:
// mats: 0=aggW, 1=uW1[:128], 2=uW1[128:], 3=uW2, 4=resW
__device__ __align__(16) unsigned char g_wt[5][2][TBYTES];

// ---------------- packed f32x2 helpers (gate kernel) --------------------------
__device__ __forceinline__ ull pack_dup(float a) {
    unsigned int au = __float_as_uint(a);
    ull r; asm("mov.b64 %0, {%1, %1};" : "=l"(r) : "r"(au)); return r;
}
__device__ __forceinline__ ull pack2(float lo, float hi) {
    ull r; asm("mov.b64 %0, {%1, %2};" : "=l"(r) : "r"(__float_as_uint(lo)), "r"(__float_as_uint(hi))); return r;
}
__device__ __forceinline__ void fma2(ull& d, ull a, ull b) {
    asm("fma.rn.f32x2 %0, %1, %2, %0;" : "+l"(d) : "l"(a), "l"(b));
}
__device__ __forceinline__ ull mul2(ull a, ull b) {
    ull r; asm("mul.rn.f32x2 %0, %1, %2;" : "=l"(r) : "l"(a), "l"(b)); return r;
}
__device__ __forceinline__ void unpack2(ull v, float& lo, float& hi) {
    unsigned int l, h;
    asm("mov.b64 {%0, %1}, %2;" : "=r"(l), "=r"(h) : "l"(v));
    lo = __uint_as_float(l); hi = __uint_as_float(h);
}

// ---------------- sigmoid LUT --------------------------------------------------
__device__ __forceinline__ float lut_sigma_g(float z) {
    float t = fminf(fmaxf(fmaf(z, 128.f, 1024.f), 0.f), 2047.99f);
    float2 e = __ldg(&g_lut[(int)t]);
    return fmaf(e.y, t, e.x);
}

// ---------------- bf16 mma.sync (sm_80+ baseline; compiles for sm_103) --------
#define MMA4(c, a, b0, b1) \
    asm volatile("mma.sync.aligned.m16n8k16.row.col.f32.bf16.bf16.f32 " \
        "{%0,%1,%2,%3}, {%4,%5,%6,%7}, {%8,%9}, {%0,%1,%2,%3};" \
        : "+f"((c)[0]), "+f"((c)[1]), "+f"((c)[2]), "+f"((c)[3]) \
        : "r"((a)[0]), "r"((a)[1]), "r"((a)[2]), "r"((a)[3]), "r"(b0), "r"(b1))

// A-fragments for this warp's 16 rows (one hi OR lo tile), PTX m16n8k16 layout:
// a0 = (row g, k = tig*2..+1 + s*16), a1 = row g+8, a2 = k+8, a3 = row g+8, k+8
__device__ __forceinline__ void load_afrag(unsigned int* af, const char* At,
                                           int warp, int g, int tig) {
    const char* base = At + ((warp * 16 + g) * TSTRIDE + tig * 2) * 2;
#pragma unroll
    for (int s = 0; s < 8; s++) {
        const char* p = base + s * 32;
        af[s * 4 + 0] = *(const unsigned int*)(p);
        af[s * 4 + 1] = *(const unsigned int*)(p + 8 * TSTRIDE * 2);
        af[s * 4 + 2] = *(const unsigned int*)(p + 16);
        af[s * 4 + 3] = *(const unsigned int*)(p + 8 * TSTRIDE * 2 + 16);
    }
}

// one 128x128x128 GEMM accumulation (3-term bf16 split) for this warp
__device__ __forceinline__ void mma_phase(float* acc,
                                          const unsigned int* afH, const unsigned int* afL,
                                          const char* Wh, const char* Wl, int g, int tig) {
#pragma unroll
    for (int nt = 0; nt < 16; nt++) {
        float* c = acc + nt * 4;
        const char* bh = Wh + ((nt * 8 + g) * TSTRIDE + tig * 2) * 2;
        const char* bl = Wl + ((nt * 8 + g) * TSTRIDE + tig * 2) * 2;
#pragma unroll
        for (int s = 0; s < 8; s++) {
            unsigned int b0h = *(const unsigned int*)(bh + s * 32);
            unsigned int b1h = *(const unsigned int*)(bh + s * 32 + 16);
            unsigned int b0l = *(const unsigned int*)(bl + s * 32);
            unsigned int b1l = *(const unsigned int*)(bl + s * 32 + 16);
            MMA4(c, &afH[s * 4], b0h, b1h);
            MMA4(c, &afH[s * 4], b0l, b1l);
            MMA4(c, &afL[s * 4], b0h, b1h);
        }
    }
}

// fp32 [128 rows] tile -> bf16 hi/lo smem tiles (256 threads, linear layout)
__device__ __forceinline__ void conv_tile256(char* hi, char* lo,
                                             const float* __restrict__ src,
                                             int row0, int n, int tid) {
#pragma unroll
    for (int i = 0; i < 8; i++) {
        int ch = tid + 256 * i;          // 2048 chunks of 8 floats
        int row = ch >> 4, part = ch & 15;
        int gr = row0 + row;
        float4 v0 = make_float4(0.f, 0.f, 0.f, 0.f);
        float4 v1 = make_float4(0.f, 0.f, 0.f, 0.f);
        if (gr < n) {
            const float4* p = (const float4*)(src + gr * DD + part * 8);
            v0 = __ldg(p);
            v1 = __ldg(p + 1);
        }
        float s[8];
        s[0] = v0.x; s[1] = v0.y; s[2] = v0.z; s[3] = v0.w;
        s[4] = v1.x; s[5] = v1.y; s[6] = v1.z; s[7] = v1.w;
        union { uint4 u; __nv_bfloat16 h[8]; } H, L;
#pragma unroll
        for (int j = 0; j < 8; j++) {
            __nv_bfloat16 hh = __float2bfloat16(s[j]);
            H.h[j] = hh;
            L.h[j] = __float2bfloat16(s[j] - __bfloat162float(hh));
        }
        int off = (row * TSTRIDE + part * 8) * 2;
        *(uint4*)(hi + off) = H.u;
        *(uint4*)(lo + off) = L.u;
    }
}

// copy pre-built weight tiles global -> smem (256 threads)
__device__ __forceinline__ void load_wt256(char* hi, char* lo,
                                           const unsigned char* gh,
                                           const unsigned char* gl, int tid) {
#pragma unroll
    for (int i = 0; i < 9; i++) {
        int idx = tid + 256 * i;
        if (idx < TBYTES / 16) {
            ((uint4*)hi)[idx] = __ldg((const uint4*)gh + idx);
            ((uint4*)lo)[idx] = __ldg((const uint4*)gl + idx);
        }
    }
}

// ---------------- LUT build + count zero ---------------------------------------
__global__ void k_lut_zcnt(int n) {
    int stride = blockDim.x * gridDim.x;
    for (int i = threadIdx.x + blockIdx.x * blockDim.x; i <= LUTN; i += stride) {
        float z0 = -8.f + (float)i * (16.f / LUTN);
        float z1 = z0 + (16.f / LUTN);
        float s0 = 1.f / (1.f + expf(-z0));
        float s1 = 1.f / (1.f + expf(-z1));
        float d  = s1 - s0;
        g_lut[i] = make_float2(s0 - (float)i * d, d);
    }
    for (int i = threadIdx.x + blockIdx.x * blockDim.x; i < NNL; i += stride) {
        float z = -8.f + ((float)i + 0.5f) * (16.f / NNL);
        g_nn[i] = 1.f / (1.f + expf(-z));
    }
    for (int i = threadIdx.x + blockIdx.x * blockDim.x; i < n; i += stride)
        g_cnti[i] = 0;
}

// ---------------- weight prep: transpose + bf16 split ---------------------------
__global__ void k_wprep(const float* __restrict__ aggW, const float* __restrict__ uW1,
                        const float* __restrict__ uW2, const float* __restrict__ resW) {
    int idx = threadIdx.x + blockIdx.x * blockDim.x;
    if (idx >= 5 * 16384) return;
    int mat = idx >> 14, e = idx & 16383;
    int k = e >> 7, col = e & 127;
    const float* src = (mat == 0) ? aggW : (mat == 1) ? uW1 : (mat == 2) ? (uW1 + 16384)
                     : (mat == 3) ? uW2 : resW;
    float v = __ldg(&src[k * DD + col]);
    __nv_bfloat16 h = __float2bfloat16(v);
    __nv_bfloat16 l = __float2bfloat16(v - __bfloat162float(h));
    int off = (col * TSTRIDE + k) * 2;   // [N rows][K cols]
    *(__nv_bfloat16*)(&g_wt[mat][0][off]) = h;
    *(__nv_bfloat16*)(&g_wt[mat][1][off]) = l;
}

// ---------------- CSR build ------------------------------------------------------
__global__ void k_count(const int* __restrict__ ei, int E) {
    int stride = blockDim.x * gridDim.x;
    for (int i = threadIdx.x + blockIdx.x * blockDim.x; i < E; i += stride)
        atomicAdd(&g_cnti[__ldg(&ei[E + i])], 1);
}

__global__ void __launch_bounds__(1024)
k_scan_fused(int n, int E) {
    __shared__ int sh[1024];
    int t = threadIdx.x;
    int len = (n + 1023) / 1024;
    int s = t * len;
    int e = min(s + len, n);
    int sum = 0;
    for (int i = s; i < e; i++) sum += g_cnti[i];
    sh[t] = sum;
    __syncthreads();
    for (int o = 1; o < 1024; o <<= 1) {
        int u = (t >= o) ? sh[t - o] : 0;
        __syncthreads();
        sh[t] += u;
        __syncthreads();
    }
    int excl = sh[t] - sum;
    for (int i = s; i < e; i++) {
        int c = g_cnti[i];
        g_rows[i] = excl;
        g_cur[i]  = excl;
        excl += c;
    }
    if (t == 0) g_rows[n] = E;
}

// ---------------- edge gate + CSR permute (thread per edge, NN sigma) ------------
__global__ void __launch_bounds__(256)
k_gate(const int* __restrict__ ei, const float* __restrict__ ea,
       const float* __restrict__ W1, const float* __restrict__ b1,
       const float* __restrict__ W2, const float* __restrict__ b2p, int E) {
    __shared__ float nn[NNL];
    __shared__ ull w1s[4][64];
    __shared__ ull b1s[64];
    __shared__ ull w2s[64];

    for (int i = threadIdx.x; i < NNL; i += blockDim.x) nn[i] = g_nn[i];
    if (threadIdx.x < 64) {
        int c2 = threadIdx.x;
#pragma unroll
        for (int k = 0; k < 4; k++)
            w1s[k][c2] = __ldg((const ull*)(W1 + k * DD) + c2);
        b1s[c2] = __ldg((const ull*)b1 + c2);
        w2s[c2] = __ldg((const ull*)W2 + c2);
    }
    __syncthreads();

    float b2v = __ldg(b2p);
    int stride = blockDim.x * gridDim.x;

    for (int e = threadIdx.x + blockIdx.x * blockDim.x; e < E; e += stride) {
        int src = __ldg(&ei[e]);
        int dst = __ldg(&ei[E + e]);
        float4 a = __ldg((const float4*)(ea + 4 * e));
        ull ax = pack_dup(a.x), ay = pack_dup(a.y);
        ull az = pack_dup(a.z), aw = pack_dup(a.w);

        ull dot2 = 0ull;
#pragma unroll 16
        for (int c2 = 0; c2 < 64; c2++) {
            ull zz = b1s[c2];
            fma2(zz, ax, w1s[0][c2]);
            fma2(zz, ay, w1s[1][c2]);
            fma2(zz, az, w1s[2][c2]);
            fma2(zz, aw, w1s[3][c2]);
            float z0, z1;
            unpack2(zz, z0, z1);
            float t0 = fminf(fmaxf(fmaf(z0, 512.f, 4096.f), 0.f), 8191.f);
            float t1 = fminf(fmaxf(fmaf(z1, 512.f, 4096.f), 0.f), 8191.f);
            ull zs = mul2(zz, pack2(nn[(int)t0], nn[(int)t1]));
            fma2(dot2, zs, w2s[c2]);
        }
        float d0, d1;
        unpack2(dot2, d0, d1);
        float zg = d0 + d1 + b2v;
        float tg = fminf(fmaxf(fmaf(zg, 512.f, 4096.f), 0.f), 8191.f);
        float ew = nn[(int)tg];

        int pos = atomicAdd(&g_cur[dst], 1);
        g_csr_src[pos] = src;
        g_csr_w[pos]   = ew;
    }
}

// ---------------- gather (warp per node) -----------------------------------------
__global__ void __launch_bounds__(256)
k_gather(int n) {
    int lane  = threadIdx.x & 31;
    int w     = (blockIdx.x * blockDim.x + threadIdx.x) >> 5;
    int nwarp = (gridDim.x * blockDim.x) >> 5;

    for (int i = w; i < n; i += nwarp) {
        int s = g_rows[i], e = g_rows[i + 1];
        float4 a0 = make_float4(0.f, 0.f, 0.f, 0.f);
        float4 a1 = make_float4(0.f, 0.f, 0.f, 0.f);
        float4 a2 = make_float4(0.f, 0.f, 0.f, 0.f);
        float4 a3 = make_float4(0.f, 0.f, 0.f, 0.f);
        int j = s;
        for (; j + 3 < e; j += 4) {
            int   s0 = __ldg(&g_csr_src[j]);
            int   s1 = __ldg(&g_csr_src[j + 1]);
            int   s2 = __ldg(&g_csr_src[j + 2]);
            int   s3 = __ldg(&g_csr_src[j + 3]);
            float w0 = __ldg(&g_csr_w[j]);
            float w1 = __ldg(&g_csr_w[j + 1]);
            float w2 = __ldg(&g_csr_w[j + 2]);
            float w3 = __ldg(&g_csr_w[j + 3]);
            float4 v0 = __ldg((const float4*)(g_ax + s0 * DD + lane * 4));
            float4 v1 = __ldg((const float4*)(g_ax + s1 * DD + lane * 4));
            float4 v2 = __ldg((const float4*)(g_ax + s2 * DD + lane * 4));
            float4 v3 = __ldg((const float4*)(g_ax + s3 * DD + lane * 4));
            a0.x = fmaf(w0, v0.x, a0.x); a0.y = fmaf(w0, v0.y, a0.y);
            a0.z = fmaf(w0, v0.z, a0.z); a0.w = fmaf(w0, v0.w, a0.w);
            a1.x = fmaf(w1, v1.x, a1.x); a1.y = fmaf(w1, v1.y, a1.y);
            a1.z = fmaf(w1, v1.z, a1.z); a1.w = fmaf(w1, v1.w, a1.w);
            a2.x = fmaf(w2, v2.x, a2.x); a2.y = fmaf(w2, v2.y, a2.y);
            a2.z = fmaf(w2, v2.z, a2.z); a2.w = fmaf(w2, v2.w, a2.w);
            a3.x = fmaf(w3, v3.x, a3.x); a3.y = fmaf(w3, v3.y, a3.y);
            a3.z = fmaf(w3, v3.z, a3.z); a3.w = fmaf(w3, v3.w, a3.w);
        }
        for (; j < e; j++) {
            int   s0 = __ldg(&g_csr_src[j]);
            float w0 = __ldg(&g_csr_w[j]);
            float4 v0 = __ldg((const float4*)(g_ax + s0 * DD + lane * 4));
            a0.x = fmaf(w0, v0.x, a0.x); a0.y = fmaf(w0, v0.y, a0.y);
            a0.z = fmaf(w0, v0.z, a0.z); a0.w = fmaf(w0, v0.w, a0.w);
        }
        float rv = 1.f / fmaxf((float)(e - s), 1.f);
        float4 o;
        o.x = (a0.x + a1.x + a2.x + a3.x) * rv;
        o.y = (a0.y + a1.y + a2.y + a3.y) * rv;
        o.z = (a0.z + a1.z + a2.z + a3.z) * rv;
        o.w = (a0.w + a1.w + a2.w + a3.w) * rv;
        *(float4*)(g_agg + i * DD + lane * 4) = o;
    }
}

// ---------------- K1 (HMMA): g_ax = silu(x @ agg_W + b) --------------------------
// smem: bias 512B, then AH, AL, WH, WL tiles -> 512 + 4*34816 = 139776
__global__ void __launch_bounds__(256)
k_agg_m(const float* __restrict__ x, const float* __restrict__ bias, int n) {
    extern __shared__ char sm[];
    const int O_B = 0, O_AH = 512, O_AL = O_AH + TBYTES,
              O_WH = O_AL + TBYTES, O_WL = O_WH + TBYTES;
    int tid = threadIdx.x;
    int row0 = blockIdx.x * 128;

    if (tid < 128) ((float*)(sm + O_B))[tid] = __ldg(&bias[tid]);
    conv_tile256(sm + O_AH, sm + O_AL, x, row0, n, tid);
    load_wt256(sm + O_WH, sm + O_WL, g_wt[0][0], g_wt[0][1], tid);
    __syncthreads();

    int lane = tid & 31, warp = tid >> 5;
    int g = lane >> 2, tig = lane & 3;

    unsigned int afH[32], afL[32];
    load_afrag(afH, sm + O_AH, warp, g, tig);
    load_afrag(afL, sm + O_AL, warp, g, tig);

    float acc[64];
#pragma unroll
    for (int i = 0; i < 64; i++) acc[i] = 0.f;
    mma_phase(acc, afH, afL, sm + O_WH, sm + O_WL, g, tig);

    const float* bs = (const float*)(sm + O_B);
    int r_hi = row0 + warp * 16 + g;
    int r_lo = r_hi + 8;
#pragma unroll
    for (int nt = 0; nt < 16; nt++) {
        int c0 = nt * 8 + tig * 2;
        float b0 = bs[c0], b1v = bs[c0 + 1];
        if (r_hi < n) {
            float z0 = acc[nt * 4 + 0] + b0, z1 = acc[nt * 4 + 1] + b1v;
            float2 v = make_float2(z0 * lut_sigma_g(z0), z1 * lut_sigma_g(z1));
            *(float2*)(g_ax + r_hi * DD + c0) = v;
        }
        if (r_lo < n) {
            float z0 = acc[nt * 4 + 2] + b0, z1 = acc[nt * 4 + 3] + b1v;
            float2 v = make_float2(z0 * lut_sigma_g(z0), z1 * lut_sigma_g(z1));
            *(float2*)(g_ax + r_lo * DD + c0) = v;
        }
    }
}

// ---------------- fused update (HMMA): 4 chained GEMMs + LN ----------------------
// smem: params 2048B (b1,b2,lng,lnb), tiles XH,XL,TH,TL,WH,WL -> 2048 + 6*34816 = 210944
__global__ void __launch_bounds__(256)
k_upd12_m(const float* __restrict__ x,
          const float* __restrict__ b1, const float* __restrict__ b2,
          const float* __restrict__ lng, const float* __restrict__ lnb,
          float* __restrict__ out, int n) {
    extern __shared__ char sm[];
    const int O_B1 = 0, O_B2 = 512, O_LG = 1024, O_LB = 1536,
              O_XH = 2048, O_XL = O_XH + TBYTES, O_TH = O_XL + TBYTES,
              O_TL = O_TH + TBYTES, O_WH = O_TL + TBYTES, O_WL = O_WH + TBYTES;
    int tid = threadIdx.x;
    int row0 = blockIdx.x * 128;

    if (tid < 128) {
        ((float*)(sm + O_B1))[tid] = __ldg(&b1[tid]);
        ((float*)(sm + O_B2))[tid] = __ldg(&b2[tid]);
        ((float*)(sm + O_LG))[tid] = __ldg(&lng[tid]);
        ((float*)(sm + O_LB))[tid] = __ldg(&lnb[tid]);
    }
    conv_tile256(sm + O_XH, sm + O_XL, x, row0, n, tid);
    conv_tile256(sm + O_TH, sm + O_TL, g_agg, row0, n, tid);
    load_wt256(sm + O_WH, sm + O_WL, g_wt[1][0], g_wt[1][1], tid);
    __syncthreads();

    int lane = tid & 31, warp = tid >> 5;
    int g = lane >> 2, tig = lane & 3;

    unsigned int afH[32], afL[32];
    float acc[64];
#pragma unroll
    for (int i = 0; i < 64; i++) acc[i] = 0.f;

    // phase A: x @ W1a
    load_afrag(afH, sm + O_XH, warp, g, tig);
    load_afrag(afL, sm + O_XL, warp, g, tig);
    mma_phase(acc, afH, afL, sm + O_WH, sm + O_WL, g, tig);
    __syncthreads();

    // phase B: agg @ W1b
    load_wt256(sm + O_WH, sm + O_WL, g_wt[2][0], g_wt[2][1], tid);
    __syncthreads();
    load_afrag(afH, sm + O_TH, warp, g, tig);
    load_afrag(afL, sm + O_TL, warp, g, tig);
    mma_phase(acc, afH, afL, sm + O_WH, sm + O_WL, g, tig);
    __syncthreads();   // everyone done reading T and W tiles

    // h1 = silu(acc + b1) -> bf16 hi/lo back into T tiles; load W2
    {
        const float* b1s = (const float*)(sm + O_B1);
        int r_hi = warp * 16 + g;       // local tile rows
#pragma unroll
        for (int nt = 0; nt < 16; nt++) {
            int c0 = nt * 8 + tig * 2;
            float bb0 = b1s[c0], bb1 = b1s[c0 + 1];
#pragma unroll
            for (int half = 0; half < 2; half++) {
                int r = r_hi + half * 8;
                float z0 = acc[nt * 4 + half * 2 + 0] + bb0;
                float z1 = acc[nt * 4 + half * 2 + 1] + bb1;
                float v0 = z0 * lut_sigma_g(z0);
                float v1 = z1 * lut_sigma_g(z1);
                __nv_bfloat16 h0 = __float2bfloat16(v0);
                __nv_bfloat16 h1 = __float2bfloat16(v1);
                __nv_bfloat16 l0 = __float2bfloat16(v0 - __bfloat162float(h0));
                __nv_bfloat16 l1 = __float2bfloat16(v1 - __bfloat162float(h1));
                unsigned int hp = ((unsigned int)__bfloat16_as_ushort(h1) << 16)
                                | __bfloat16_as_ushort(h0);
                unsigned int lp = ((unsigned int)__bfloat16_as_ushort(l1) << 16)
                                | __bfloat16_as_ushort(l0);
                int off = (r * TSTRIDE + c0) * 2;
                *(unsigned int*)(sm + O_TH + off) = hp;
                *(unsigned int*)(sm + O_TL + off) = lp;
            }
        }
        load_wt256(sm + O_WH, sm + O_WL, g_wt[3][0], g_wt[3][1], tid);
    }
    __syncthreads();

    // phase C: h1 @ W2
#pragma unroll
    for (int i = 0; i < 64; i++) acc[i] = 0.f;
    load_afrag(afH, sm + O_TH, warp, g, tig);
    load_afrag(afL, sm + O_TL, warp, g, tig);
    mma_phase(acc, afH, afL, sm + O_WH, sm + O_WL, g, tig);
    __syncthreads();

    // phase D: x @ resW
    load_wt256(sm + O_WH, sm + O_WL, g_wt[4][0], g_wt[4][1], tid);
    __syncthreads();
    load_afrag(afH, sm + O_XH, warp, g, tig);
    load_afrag(afL, sm + O_XL, warp, g, tig);
    mma_phase(acc, afH, afL, sm + O_WH, sm + O_WL, g, tig);

    // epilogue: z = acc + b2, per-row LayerNorm via quad reduction
    {
        const float* b2s = (const float*)(sm + O_B2);
        const float* lg  = (const float*)(sm + O_LG);
        const float* lb  = (const float*)(sm + O_LB);

        float sA = 0.f, qA = 0.f, sB = 0.f, qB = 0.f;
#pragma unroll
        for (int nt = 0; nt < 16; nt++) {
            int c0 = nt * 8 + tig * 2;
            float bb0 = b2s[c0], bb1 = b2s[c0 + 1];
            float z0 = acc[nt * 4 + 0] + bb0, z1 = acc[nt * 4 + 1] + bb1;
            float z2 = acc[nt * 4 + 2] + bb0, z3 = acc[nt * 4 + 3] + bb1;
            acc[nt * 4 + 0] = z0; acc[nt * 4 + 1] = z1;
            acc[nt * 4 + 2] = z2; acc[nt * 4 + 3] = z3;
            sA += z0 + z1; qA += z0 * z0 + z1 * z1;
            sB += z2 + z3; qB += z2 * z2 + z3 * z3;
        }
#pragma unroll
        for (int m = 1; m <= 2; m <<= 1) {
            sA += __shfl_xor_sync(0xffffffffu, sA, m);
            qA += __shfl_xor_sync(0xffffffffu, qA, m);
            sB += __shfl_xor_sync(0xffffffffu, sB, m);
            qB += __shfl_xor_sync(0xffffffffu, qB, m);
        }
        float muA = sA * (1.f / 128.f);
        float rsA = rsqrtf(qA * (1.f / 128.f) - muA * muA + LNEPS);
        float muB = sB * (1.f / 128.f);
        float rsB = rsqrtf(qB * (1.f / 128.f) - muB * muB + LNEPS);

        int r_hi = row0 + warp * 16 + g;
        int r_lo = r_hi + 8;
#pragma unroll
        for (int nt = 0; nt < 16; nt++) {
            int c0 = nt * 8 + tig * 2;
            float g0 = lg[c0], g1 = lg[c0 + 1];
            float o0 = lb[c0], o1 = lb[c0 + 1];
            if (r_hi < n) {
                float2 v;
                v.x = (acc[nt * 4 + 0] - muA) * rsA * g0 + o0;
                v.y = (acc[nt * 4 + 1] - muA) * rsA * g1 + o1;
                *(float2*)(out + r_hi * DD + c0) = v;
            }
            if (r_lo < n) {
                float2 v;
                v.x = (acc[nt * 4 + 2] - muB) * rsB * g0 + o0;
                v.y = (acc[nt * 4 + 3] - muB) * rsB * g1 + o1;
                *(float2*)(out + r_lo * DD + c0) = v;
            }
        }
    }
}

// ---------------- launch -----------------------------------------------------------
extern "C" void kernel_launch(void* const* d_in, const int* in_sizes, int n_in,
                              void* d_out, int out_size) {
    const float* x    = (const float*)d_in[0];
    const int*   ei   = (const int*)  d_in[1];
    const float* ea   = (const float*)d_in[2];
    const float* aggW = (const float*)d_in[3];
    const float* aggb = (const float*)d_in[4];
    const float* eW1  = (const float*)d_in[5];
    const float* eb1  = (const float*)d_in[6];
    const float* eW2  = (const float*)d_in[7];
    const float* eb2  = (const float*)d_in[8];
    const float* uW1  = (const float*)d_in[9];
    const float* ub1  = (const float*)d_in[10];
    const float* uW2  = (const float*)d_in[11];
    const float* ub2  = (const float*)d_in[12];
    const float* lng  = (const float*)d_in[13];
    const float* lnb  = (const float*)d_in[14];
    const float* resW = (const float*)d_in[15];

    int n = in_sizes[0] / DD;
    int E = in_sizes[2] / 4;

    const int SMEM_A = 512 + 4 * TBYTES;     // 139776
    const int SMEM_U = 2048 + 6 * TBYTES;    // 210944
    cudaFuncSetAttribute(k_agg_m,   cudaFuncAttributeMaxDynamicSharedMemorySize, SMEM_A);
    cudaFuncSetAttribute(k_upd12_m, cudaFuncAttributeMaxDynamicSharedMemorySize, SMEM_U);

    int gblocks = (n + 127) / 128;   // 782

    // 4th launch (k_agg_m) is the profiled one -> verify HMMA path
    k_lut_zcnt<<<512, 256>>>(n);                                    // 1
    k_count<<<1024, 256>>>(ei, E);                                  // 2
    k_wprep<<<320, 256>>>(aggW, uW1, uW2, resW);                    // 3
    k_agg_m<<<gblocks, 256, SMEM_A>>>(x, aggb, n);                  // 4 <- profiled
    k_scan_fused<<<1, 1024>>>(n, E);                                // 5
    k_gate<<<1480, 256>>>(ei, ea, eW1, eb1, eW2, eb2, E);           // 6
    k_gather<<<2048, 256>>>(n);                                     // 7
    k_upd12_m<<<gblocks, 256, SMEM_U>>>(x, ub1, ub2, lng, lnb,
                                        (float*)d_out, n);          // 8
}